// round 9
// baseline (speedup 1.0000x reference)
#include <cuda_runtime.h>
#include <cuda_fp16.h>
#include <math.h>
#include <string.h>

#define NN 100000
#define NE 3200000
#define FIN 128
#define RS 16          // fp32 row stride (64 B)
#define RH 8           // half2 per fp16 row (32 B)
#define NB 1000
#define SCAT_BLOCKS ((NE / 2 + 255) / 256)
#define GEMM_BLOCKS ((NN + 255) / 256)

// Scratch (allocation-free: __device__ globals; zero-initialized at load;
// k_final/k_head restore the zero-invariants at the end of every call)
static __device__ float   g_xa[NN * RS];          // x @ W1[:128] (self, fp32)
static __device__ __half2 g_xbh[NN * RH];         // x @ W1[128:] (fp16)
static __device__ float   g_h1a[NN * RS];         // h1 @ W2[:10] (fp32)
static __device__ __half2 g_h1bh[NN * RH];        // h1 @ W2[10:] (fp16)
static __device__ float   g_h2[NN * RS];          // layer-2 output
static __device__ float   g_pool[NB * RS];        // batch pool ([10] = count)
static __device__ int     g_deg[NN];              // in-degree (zeroed by k_final)
static __device__ int     g_start[NN];            // CSR starts
static __device__ int     g_cursor[NN];
static __device__ int     g_adj[NE];              // CSR adjacency

__device__ __forceinline__ unsigned h2u(__half2 h) {
    unsigned u; memcpy(&u, &h, 4); return u;
}
__device__ __forceinline__ unsigned long long pk2(float lo, float hi) {
    unsigned long long r;
    asm("mov.b64 %0, {%1, %2};" : "=l"(r) : "f"(lo), "f"(hi));
    return r;
}
__device__ __forceinline__ void fma2(unsigned long long& d, unsigned long long a,
                                     unsigned long long b) {
    asm("fma.rn.f32x2 %0, %1, %2, %0;" : "+l"(d) : "l"(a), "l"(b));
}
__device__ __forceinline__ float2 upk2(unsigned long long v) {
    float2 f;
    asm("mov.b64 {%0, %1}, %2;" : "=f"(f.x), "=f"(f.y) : "l"(v));
    return f;
}

// ---------------------------------------------------------------------------
__global__ __launch_bounds__(256) void k_hist(const int* __restrict__ dst) {
    int t = blockIdx.x * blockDim.x + threadIdx.x;
    if (t >= NE / 4) return;
    int4 d4 = __ldg((const int4*)dst + t);
    atomicAdd(&g_deg[d4.x], 1);
    atomicAdd(&g_deg[d4.y], 1);
    atomicAdd(&g_deg[d4.z], 1);
    atomicAdd(&g_deg[d4.w], 1);
}

// ---------------------------------------------------------------------------
// One-shot scan: each block directly reduces all preceding degrees for its
// cross-block prefix (L2-resident, all 98 blocks concurrent), then local scan.
__global__ __launch_bounds__(256) void k_scan() {
    int t = threadIdx.x, blk = blockIdx.x;
    __shared__ int s_red[8];
    __shared__ int s_pre;
    // cross-block prefix: sum deg[0 .. blk*1024)
    int pre = 0;
    for (int i = t; i < blk * 1024; i += 256) pre += g_deg[i];
#pragma unroll
    for (int off = 16; off; off >>= 1) pre += __shfl_xor_sync(0xffffffffu, pre, off);
    if ((t & 31) == 0) s_red[t >> 5] = pre;
    __syncthreads();
    if (t == 0) {
        int r = 0;
#pragma unroll
        for (int i = 0; i < 8; i++) r += s_red[i];
        s_pre = r;
    }
    __syncthreads();
    // local exclusive scan of this block's 1024 degrees
    int base = blk * 1024 + t * 4;
    int vals[4]; int tsum = 0;
#pragma unroll
    for (int j = 0; j < 4; j++) {
        int i = base + j;
        vals[j] = (i < NN) ? g_deg[i] : 0;
        tsum += vals[j];
    }
    int lane = t & 31, wid = t >> 5;
    int incl = tsum;
#pragma unroll
    for (int off = 1; off < 32; off <<= 1) {
        int u = __shfl_up_sync(0xffffffffu, incl, off);
        if (lane >= off) incl += u;
    }
    __shared__ int ws[8], wo[8];
    if (lane == 31) ws[wid] = incl;
    __syncthreads();
    if (t == 0) { int r = 0; for (int i = 0; i < 8; i++) { wo[i] = r; r += ws[i]; } }
    __syncthreads();
    int excl = s_pre + wo[wid] + incl - tsum;
#pragma unroll
    for (int j = 0; j < 4; j++) {
        int i = base + j;
        if (i < NN) { g_start[i] = excl; g_cursor[i] = excl; excl += vals[j]; }
    }
}

// ---------------------------------------------------------------------------
// Fused: blocks [0, SCAT_BLOCKS) scatter edges; rest run layer-1 GEMM
// (thread-per-node, packed-pair weights in smem, FFMA2).
__global__ __launch_bounds__(256) void k_scatter_gemm(const int* __restrict__ src,
                                                      const int* __restrict__ dst,
                                                      const float* __restrict__ x,
                                                      const float* __restrict__ W1) {
    if (blockIdx.x < SCAT_BLOCKS) {
        int t = blockIdx.x * 256 + threadIdx.x;
        if (t >= NE / 2) return;
        int2 s2 = __ldg((const int2*)src + t);
        int2 d2 = __ldg((const int2*)dst + t);
        int p0 = atomicAdd(&g_cursor[d2.x], 1);
        int p1 = atomicAdd(&g_cursor[d2.y], 1);
        g_adj[p0] = s2.x;
        g_adj[p1] = s2.y;
        return;
    }
    // ---- GEMM path: swp[o2*128 + k] = pack(wt[2o2][k], wt[2o2+1][k]) ----
    __shared__ unsigned long long swp[10 * 128];
    int tid = threadIdx.x;
    for (int i = tid; i < 1280; i += 256) {
        int o2 = i >> 7, k = i & 127;
        int oA = 2 * o2, oB = 2 * o2 + 1;
        float wA = (oA < 10) ? __ldg(&W1[k * 10 + oA]) : __ldg(&W1[(k + 128) * 10 + oA - 10]);
        float wB = (oB < 10) ? __ldg(&W1[k * 10 + oB]) : __ldg(&W1[(k + 128) * 10 + oB - 10]);
        swp[i] = pk2(wA, wB);
    }
    __syncthreads();
    int n = (blockIdx.x - SCAT_BLOCKS) * 256 + tid;
    if (n >= NN) return;
    const float4* xr = (const float4*)(x + (size_t)n * FIN);
    const ulonglong2* swv = (const ulonglong2*)swp;   // swv[o2*64 + k2]
    unsigned long long acc2[10];
#pragma unroll
    for (int o = 0; o < 10; o++) acc2[o] = pk2(0.f, 0.f);
#pragma unroll 4
    for (int k4 = 0; k4 < 32; k4++) {
        float4 xv = __ldg(xr + k4);
        unsigned long long x0 = pk2(xv.x, xv.x), x1 = pk2(xv.y, xv.y);
        unsigned long long x2 = pk2(xv.z, xv.z), x3 = pk2(xv.w, xv.w);
#pragma unroll
        for (int o2 = 0; o2 < 10; o2++) {
            ulonglong2 wa = swv[o2 * 64 + 2 * k4];
            ulonglong2 wb = swv[o2 * 64 + 2 * k4 + 1];
            fma2(acc2[o2], x0, wa.x);
            fma2(acc2[o2], x1, wa.y);
            fma2(acc2[o2], x2, wb.x);
            fma2(acc2[o2], x3, wb.y);
        }
    }
    float2 r[10];
#pragma unroll
    for (int o = 0; o < 10; o++) r[o] = upk2(acc2[o]);
    float* pa = g_xa + (size_t)n * RS;
    *(float4*)(pa)     = make_float4(r[0].x, r[0].y, r[1].x, r[1].y);
    *(float4*)(pa + 4) = make_float4(r[2].x, r[2].y, r[3].x, r[3].y);
    *(float2*)(pa + 8) = make_float2(r[4].x, r[4].y);
    uint4 u;
    u.x = h2u(__floats2half2_rn(r[5].x, r[5].y));
    u.y = h2u(__floats2half2_rn(r[6].x, r[6].y));
    u.z = h2u(__floats2half2_rn(r[7].x, r[7].y));
    u.w = h2u(__floats2half2_rn(r[8].x, r[8].y));
    *(uint4*)(g_xbh + (size_t)n * RH) = u;
    ((unsigned*)(g_xbh + (size_t)n * RH))[4] = h2u(__floats2half2_rn(r[9].x, r[9].y));
}

// ---------------------------------------------------------------------------
__device__ __forceinline__ void red_v4(float* p, float a, float b, float c, float d) {
    asm volatile("red.global.add.v4.f32 [%0], {%1,%2,%3,%4};"
                 :: "l"(p), "f"(a), "f"(b), "f"(c), "f"(d) : "memory");
}

// Pull aggregation (round-7 form), warp per node, fp16 rows, 4 edges per LDG.
// lane = (q = lane>>3 edge slot, idx = lane&7 -> dims 2idx, 2idx+1)
template <int PASS>
__global__ __launch_bounds__(256) void k_aggr(const float* __restrict__ W2) {
    const int lane = threadIdx.x & 31;
    const int n = (blockIdx.x * blockDim.x + threadIdx.x) >> 5;
    if (n >= NN) return;
    const int q = lane >> 3;
    const int idx = lane & 7;

    float wcol[10];
    if (PASS == 0) {
        int col = lane & 15; if (col >= 10) col = 0;
        int off = (lane >> 4) * 10;
#pragma unroll
        for (int k = 0; k < 10; k++) wcol[k] = __ldg(&W2[(k + off) * 10 + col]);
    }

    const int start = g_start[n];
    const int deg = g_deg[n];
    const __half2* buf = (PASS == 0) ? g_xbh : g_h1bh;

    float a0 = 0.f, a1 = 0.f;
    for (int base = 0; base < deg; base += 32) {
        int m = deg - base; if (m > 32) m = 32;
        int av = (base + lane < deg) ? __ldg(&g_adj[start + base + lane]) : 0;
        int groups = (m + 3) >> 2;
#pragma unroll 8
        for (int g = 0; g < groups; g++) {
            int e = 4 * g + q;
            int s = __shfl_sync(0xffffffffu, av, e & 31);
            if (e < m) {
                float2 f = __half22float2(__ldg(&buf[(size_t)s * RH + idx]));
                a0 += f.x; a1 += f.y;
            }
        }
    }
    a0 += __shfl_xor_sync(0xffffffffu, a0, 8);
    a0 += __shfl_xor_sync(0xffffffffu, a0, 16);
    a1 += __shfl_xor_sync(0xffffffffu, a1, 8);
    a1 += __shfl_xor_sync(0xffffffffu, a1, 16);

    const float inv = deg > 0 ? 1.f / (float)deg : 0.f;

    if (PASS == 0) {
        float2 xs = *(const float2*)(g_xa + (size_t)n * RS + 2 * idx);
        float h0 = fmaxf(xs.x + a0 * inv, 0.f);   // dim 2*idx
        float h1 = fmaxf(xs.y + a1 * inv, 0.f);   // dim 2*idx+1
        float o = 0.f;
#pragma unroll
        for (int k = 0; k < 10; k++) {
            float hk = (k & 1) ? __shfl_sync(0xffffffffu, h1, k >> 1)
                               : __shfl_sync(0xffffffffu, h0, k >> 1);
            o += hk * wcol[k];
        }
        int dim = lane & 15;
        float onext = __shfl_down_sync(0xffffffffu, o, 1);
        if (lane < 16) {                         // h1a, fp32
            if (dim < 10) g_h1a[(size_t)n * RS + dim] = o;
        } else if ((dim & 1) == 0 && dim < 10) { // h1b, fp16 packed
            g_h1bh[(size_t)n * RH + (dim >> 1)] = __floats2half2_rn(o, onext);
        }
    } else {
        if (lane < 5) {                          // q==0, idx 0-4 -> dims 0-9
            float2 ar = *(const float2*)(g_h1a + (size_t)n * RS + 2 * idx);
            float2 h2v;
            h2v.x = ar.x + a0 * inv;
            h2v.y = ar.y + a1 * inv;
            *(float2*)(g_h2 + (size_t)n * RS + 2 * idx) = h2v;
        }
    }
}

// ---------------------------------------------------------------------------
// Pool h2 by sorted batch id; also restore g_deg = 0 for the next replay.
__global__ __launch_bounds__(256) void k_final(const int* __restrict__ batch) {
    int n = blockIdx.x * blockDim.x + threadIdx.x;
    if (n >= NN) return;            // NN % 32 == 0
    g_deg[n] = 0;                   // invariant for next graph replay
    int lane = threadIdx.x & 31;
    const float4* hr = (const float4*)(g_h2 + (size_t)n * RS);
    float4 h0 = __ldg(hr), h1 = __ldg(hr + 1);
    float2 h2 = __ldg((const float2*)(hr + 2));
    float h[10] = {h0.x, h0.y, h0.z, h0.w, h1.x, h1.y, h1.z, h1.w, h2.x, h2.y};
    int b = __ldg(&batch[n]);
    int b0 = __shfl_sync(0xffffffffu, b, 0);
    bool uni = __all_sync(0xffffffffu, b == b0);
    if (uni) {
#pragma unroll
        for (int off = 16; off; off >>= 1)
#pragma unroll
            for (int o = 0; o < 10; o++)
                h[o] += __shfl_xor_sync(0xffffffffu, h[o], off);
        if (lane == 0) {
            float* pp = g_pool + b * RS;
            red_v4(pp,     h[0], h[1], h[2], h[3]);
            red_v4(pp + 4, h[4], h[5], h[6], h[7]);
            red_v4(pp + 8, h[8], h[9], 32.f, 0.f);
        }
    } else {
        float* pp = g_pool + b * RS;
#pragma unroll
        for (int o = 0; o < 10; o++) atomicAdd(&pp[o], h[o]);
        atomicAdd(&pp[10], 1.f);
    }
}

// ---------------------------------------------------------------------------
// Head; also restore g_pool = 0 for the next replay.
__global__ void k_head(const float* __restrict__ Wfc, float* __restrict__ out) {
    int b = blockIdx.x * blockDim.x + threadIdx.x;
    if (b >= NB) return;
    float cnt = g_pool[b * RS + 10];
    float inv = 1.f / fmaxf(cnt, 1.f);
    float v = 0.f;
#pragma unroll
    for (int o = 0; o < 10; o++)
        v += g_pool[b * RS + o] * inv * __ldg(&Wfc[o]);
    out[b] = 1.f / (1.f + expf(-v));
#pragma unroll
    for (int o = 0; o < 11; o++) g_pool[b * RS + o] = 0.f;   // invariant
}

// ---------------------------------------------------------------------------
extern "C" void kernel_launch(void* const* d_in, const int* in_sizes, int n_in,
                              void* d_out, int out_size) {
    const float* x     = (const float*)d_in[0];
    const int*   ei    = (const int*)d_in[1];   // [2, E]
    const int*   batch = (const int*)d_in[2];
    const float* W1    = (const float*)d_in[3]; // [256,10]
    const float* W2    = (const float*)d_in[4]; // [20,10]
    const float* Wfc   = (const float*)d_in[5]; // [10,1]
    float* out = (float*)d_out;

    const int* src = ei;
    const int* dst = ei + NE;

    k_hist<<<(NE / 4 + 255) / 256, 256>>>(dst);                     // 0
    k_scan<<<98, 256>>>();                                          // 1
    k_scatter_gemm<<<SCAT_BLOCKS + GEMM_BLOCKS, 256>>>(src, dst, x, W1); // 2
    k_aggr<0><<<(NN * 32 + 255) / 256, 256>>>(W2);                  // 3 <- profiled
    k_aggr<1><<<(NN * 32 + 255) / 256, 256>>>(W2);                  // 4
    k_final<<<(NN + 255) / 256, 256>>>(batch);                      // 5
    k_head<<<(NB + 255) / 256, 256>>>(Wfc, out);                    // 6
}

// round 14
// speedup vs baseline: 1.1273x; 1.1273x over previous
#include <cuda_runtime.h>
#include <cuda_fp16.h>
#include <math.h>
#include <string.h>

#define NN 100000
#define NE 3200000
#define FIN 128
#define RS 16          // fp32 row stride (64 B)
#define RH 8           // half2 per fp16 row (32 B)
#define NB 1000
#define SCAT_BLOCKS ((NE / 2 + 255) / 256)
#define GEMM_BLOCKS ((NN + 255) / 256)

// Scratch (allocation-free __device__ globals; zero-initialized at load;
// k_final/k_head restore the zero-invariants each call; row NN of the fp16
// buffers is a permanent zero row used to pad gathers).
static __device__ float   g_xa[NN * RS];            // x @ W1[:128] (self, fp32)
static __device__ __half2 g_xbh[(NN + 1) * RH];     // x @ W1[128:] (fp16)
static __device__ float   g_h1a[NN * RS];           // h1 @ W2[:10] (fp32)
static __device__ __half2 g_h1bh[(NN + 1) * RH];    // h1 @ W2[10:] (fp16)
static __device__ float   g_h2[NN * RS];            // layer-2 output
static __device__ float   g_pool[NB * RS];          // batch pool ([10] = count)
static __device__ int     g_deg[NN];                // in-degree (zeroed by k_final)
static __device__ int     g_start[NN];              // CSR starts
static __device__ int     g_cursor[NN];
static __device__ int     g_adj[NE];                // CSR adjacency

__device__ __forceinline__ unsigned h2u(__half2 h) {
    unsigned u; memcpy(&u, &h, 4); return u;
}
__device__ __forceinline__ __half2 u2h(unsigned u) {
    __half2 h; memcpy(&h, &u, 4); return h;
}
__device__ __forceinline__ unsigned long long pk2(float lo, float hi) {
    unsigned long long r;
    asm("mov.b64 %0, {%1, %2};" : "=l"(r) : "f"(lo), "f"(hi));
    return r;
}
__device__ __forceinline__ void fma2(unsigned long long& d, unsigned long long a,
                                     unsigned long long b) {
    asm("fma.rn.f32x2 %0, %1, %2, %0;" : "+l"(d) : "l"(a), "l"(b));
}
__device__ __forceinline__ float2 upk2(unsigned long long v) {
    float2 f;
    asm("mov.b64 {%0, %1}, %2;" : "=f"(f.x), "=f"(f.y) : "l"(v));
    return f;
}

// ---------------------------------------------------------------------------
__global__ __launch_bounds__(256) void k_hist(const int* __restrict__ dst) {
    int t = blockIdx.x * blockDim.x + threadIdx.x;
    if (t >= NE / 4) return;
    int4 d4 = __ldg((const int4*)dst + t);
    atomicAdd(&g_deg[d4.x], 1);
    atomicAdd(&g_deg[d4.y], 1);
    atomicAdd(&g_deg[d4.z], 1);
    atomicAdd(&g_deg[d4.w], 1);
}

// ---------------------------------------------------------------------------
// One-shot scan (scanA+B+C fused): cross-block prefix by direct reduction.
__global__ __launch_bounds__(256) void k_scan() {
    int t = threadIdx.x, blk = blockIdx.x;
    __shared__ int s_red[8];
    __shared__ int s_pre;
    int pre = 0;
    for (int i = t; i < blk * 1024; i += 256) pre += g_deg[i];
#pragma unroll
    for (int off = 16; off; off >>= 1) pre += __shfl_xor_sync(0xffffffffu, pre, off);
    if ((t & 31) == 0) s_red[t >> 5] = pre;
    __syncthreads();
    if (t == 0) {
        int r = 0;
#pragma unroll
        for (int i = 0; i < 8; i++) r += s_red[i];
        s_pre = r;
    }
    __syncthreads();
    int base = blk * 1024 + t * 4;
    int vals[4]; int tsum = 0;
#pragma unroll
    for (int j = 0; j < 4; j++) {
        int i = base + j;
        vals[j] = (i < NN) ? g_deg[i] : 0;
        tsum += vals[j];
    }
    int lane = t & 31, wid = t >> 5;
    int incl = tsum;
#pragma unroll
    for (int off = 1; off < 32; off <<= 1) {
        int u = __shfl_up_sync(0xffffffffu, incl, off);
        if (lane >= off) incl += u;
    }
    __shared__ int ws[8], wo[8];
    if (lane == 31) ws[wid] = incl;
    __syncthreads();
    if (t == 0) { int r = 0; for (int i = 0; i < 8; i++) { wo[i] = r; r += ws[i]; } }
    __syncthreads();
    int excl = s_pre + wo[wid] + incl - tsum;
#pragma unroll
    for (int j = 0; j < 4; j++) {
        int i = base + j;
        if (i < NN) { g_start[i] = excl; g_cursor[i] = excl; excl += vals[j]; }
    }
}

// ---------------------------------------------------------------------------
// Fused: blocks [0, SCAT_BLOCKS) scatter edges; rest run layer-1 GEMM.
__global__ __launch_bounds__(256) void k_scatter_gemm(const int* __restrict__ src,
                                                      const int* __restrict__ dst,
                                                      const float* __restrict__ x,
                                                      const float* __restrict__ W1) {
    if (blockIdx.x < SCAT_BLOCKS) {
        int t = blockIdx.x * 256 + threadIdx.x;
        if (t >= NE / 2) return;
        int2 s2 = __ldg((const int2*)src + t);
        int2 d2 = __ldg((const int2*)dst + t);
        int p0 = atomicAdd(&g_cursor[d2.x], 1);
        int p1 = atomicAdd(&g_cursor[d2.y], 1);
        g_adj[p0] = s2.x;
        g_adj[p1] = s2.y;
        return;
    }
    __shared__ unsigned long long swp[10 * 128];   // packed output pairs
    int tid = threadIdx.x;
    for (int i = tid; i < 1280; i += 256) {
        int o2 = i >> 7, k = i & 127;
        int oA = 2 * o2, oB = 2 * o2 + 1;
        float wA = (oA < 10) ? __ldg(&W1[k * 10 + oA]) : __ldg(&W1[(k + 128) * 10 + oA - 10]);
        float wB = (oB < 10) ? __ldg(&W1[k * 10 + oB]) : __ldg(&W1[(k + 128) * 10 + oB - 10]);
        swp[i] = pk2(wA, wB);
    }
    __syncthreads();
    int n = (blockIdx.x - SCAT_BLOCKS) * 256 + tid;
    if (n >= NN) return;
    const float4* xr = (const float4*)(x + (size_t)n * FIN);
    const ulonglong2* swv = (const ulonglong2*)swp;
    unsigned long long acc2[10];
#pragma unroll
    for (int o = 0; o < 10; o++) acc2[o] = pk2(0.f, 0.f);
#pragma unroll 4
    for (int k4 = 0; k4 < 32; k4++) {
        float4 xv = __ldg(xr + k4);
        unsigned long long x0 = pk2(xv.x, xv.x), x1 = pk2(xv.y, xv.y);
        unsigned long long x2 = pk2(xv.z, xv.z), x3 = pk2(xv.w, xv.w);
#pragma unroll
        for (int o2 = 0; o2 < 10; o2++) {
            ulonglong2 wa = swv[o2 * 64 + 2 * k4];
            ulonglong2 wb = swv[o2 * 64 + 2 * k4 + 1];
            fma2(acc2[o2], x0, wa.x);
            fma2(acc2[o2], x1, wa.y);
            fma2(acc2[o2], x2, wb.x);
            fma2(acc2[o2], x3, wb.y);
        }
    }
    float2 r[10];
#pragma unroll
    for (int o = 0; o < 10; o++) r[o] = upk2(acc2[o]);
    float* pa = g_xa + (size_t)n * RS;
    *(float4*)(pa)     = make_float4(r[0].x, r[0].y, r[1].x, r[1].y);
    *(float4*)(pa + 4) = make_float4(r[2].x, r[2].y, r[3].x, r[3].y);
    *(float2*)(pa + 8) = make_float2(r[4].x, r[4].y);
    uint4 u;
    u.x = h2u(__floats2half2_rn(r[5].x, r[5].y));
    u.y = h2u(__floats2half2_rn(r[6].x, r[6].y));
    u.z = h2u(__floats2half2_rn(r[7].x, r[7].y));
    u.w = h2u(__floats2half2_rn(r[8].x, r[8].y));
    *(uint4*)(g_xbh + (size_t)n * RH) = u;
    ((unsigned*)(g_xbh + (size_t)n * RH))[4] = h2u(__floats2half2_rn(r[9].x, r[9].y));
}

// ---------------------------------------------------------------------------
__device__ __forceinline__ void red_v4(float* p, float a, float b, float c, float d) {
    asm volatile("red.global.add.v4.f32 [%0], {%1,%2,%3,%4};"
                 :: "l"(p), "f"(a), "f"(b), "f"(c), "f"(d) : "memory");
}

// Pull aggregation, warp per node. lane = (e4 = lane>>2 edge slot,
// j = lane&3 quarter-row -> dims 4j..4j+3). 8 edges per LDG.64 group,
// HADD2 fp16 accumulation, predicate-free bulk, zero-row (NN) padded tail.
template <int PASS>
__global__ __launch_bounds__(256) void k_aggr(const float* __restrict__ W2) {
    const int lane = threadIdx.x & 31;
    const int n = (blockIdx.x * blockDim.x + threadIdx.x) >> 5;
    if (n >= NN) return;
    const int e4 = lane >> 2;
    const int j = lane & 3;

    float wcol[10];
    if (PASS == 0) {
        int col = lane & 15; if (col >= 10) col = 0;
        int off = (lane >> 4) * 10;
#pragma unroll
        for (int k = 0; k < 10; k++) wcol[k] = __ldg(&W2[(k + off) * 10 + col]);
    }

    const int start = g_start[n];
    const int deg = g_deg[n];
    const unsigned long long* bufu = (PASS == 0)
        ? (const unsigned long long*)g_xbh : (const unsigned long long*)g_h1bh;

    __half2 hacc0 = u2h(0u), hacc1 = u2h(0u);
    int base = 0;
    const int nfull = deg >> 5;
    for (int c = 0; c < nfull; c++, base += 32) {
        int av = __ldg(&g_adj[start + base + lane]);
#pragma unroll
        for (int g = 0; g < 4; g++) {
            int s = __shfl_sync(0xffffffffu, av, 8 * g + e4);
            unsigned long long v = __ldg(&bufu[(size_t)s * 4 + j]);
            hacc0 = __hadd2(hacc0, u2h((unsigned)v));
            hacc1 = __hadd2(hacc1, u2h((unsigned)(v >> 32)));
        }
    }
    const int m = deg - base;                 // 0..31 tail
    if (m > 0) {
        int av = (lane < m) ? __ldg(&g_adj[start + base + lane]) : NN;
        const int tg = (m + 7) >> 3;
        for (int g = 0; g < tg; g++) {
            int e = 8 * g + e4;
            int s = __shfl_sync(0xffffffffu, av, e & 31);
            if (e >= m) s = NN;               // zero row
            unsigned long long v = __ldg(&bufu[(size_t)s * 4 + j]);
            hacc0 = __hadd2(hacc0, u2h((unsigned)v));
            hacc1 = __hadd2(hacc1, u2h((unsigned)(v >> 32)));
        }
    }
    // fold fp16 -> fp32, reduce across the 8 edge slots (xor 4, 8, 16)
    float2 fA = __half22float2(hacc0);        // dims 4j, 4j+1
    float2 fB = __half22float2(hacc1);        // dims 4j+2, 4j+3
#pragma unroll
    for (int off = 4; off <= 16; off <<= 1) {
        fA.x += __shfl_xor_sync(0xffffffffu, fA.x, off);
        fA.y += __shfl_xor_sync(0xffffffffu, fA.y, off);
        fB.x += __shfl_xor_sync(0xffffffffu, fB.x, off);
        fB.y += __shfl_xor_sync(0xffffffffu, fB.y, off);
    }

    const float inv = deg > 0 ? 1.f / (float)deg : 0.f;

    if (PASS == 0) {
        // lane j holds dims 4j..4j+3; apply self + relu, then broadcast h
        float4 xv = __ldg((const float4*)(g_xa + (size_t)n * RS + 4 * j));
        float p0 = fmaxf(xv.x + fA.x * inv, 0.f);
        float p1 = fmaxf(xv.y + fA.y * inv, 0.f);
        float p2 = fmaxf(xv.z + fB.x * inv, 0.f);
        float p3 = fmaxf(xv.w + fB.y * inv, 0.f);
        float h[10];
        h[0] = __shfl_sync(0xffffffffu, p0, 0);
        h[1] = __shfl_sync(0xffffffffu, p1, 0);
        h[2] = __shfl_sync(0xffffffffu, p2, 0);
        h[3] = __shfl_sync(0xffffffffu, p3, 0);
        h[4] = __shfl_sync(0xffffffffu, p0, 1);
        h[5] = __shfl_sync(0xffffffffu, p1, 1);
        h[6] = __shfl_sync(0xffffffffu, p2, 1);
        h[7] = __shfl_sync(0xffffffffu, p3, 1);
        h[8] = __shfl_sync(0xffffffffu, p0, 2);
        h[9] = __shfl_sync(0xffffffffu, p1, 2);
        float o = 0.f;
#pragma unroll
        for (int k = 0; k < 10; k++) o += h[k] * wcol[k];
        int dim = lane & 15;
        float onext = __shfl_down_sync(0xffffffffu, o, 1);
        if (lane < 16) {                          // h1a, fp32
            if (dim < 10) g_h1a[(size_t)n * RS + dim] = o;
        } else if ((dim & 1) == 0 && dim < 10) {  // h1b, fp16 packed
            g_h1bh[(size_t)n * RH + (dim >> 1)] = __floats2half2_rn(o, onext);
        }
    } else {
        if (lane < 3) {                           // e4==0, j=0..2 -> dims 0-11
            float4 ar = __ldg((const float4*)(g_h1a + (size_t)n * RS + 4 * j));
            float4 h2v;
            h2v.x = ar.x + fA.x * inv;
            h2v.y = ar.y + fA.y * inv;
            h2v.z = ar.z + fB.x * inv;
            h2v.w = ar.w + fB.y * inv;
            *(float4*)(g_h2 + (size_t)n * RS + 4 * j) = h2v;
        }
    }
}

// ---------------------------------------------------------------------------
// Pool h2 by sorted batch id; restores g_deg = 0 for the next replay.
__global__ __launch_bounds__(256) void k_final(const int* __restrict__ batch) {
    int n = blockIdx.x * blockDim.x + threadIdx.x;
    if (n >= NN) return;            // NN % 32 == 0
    g_deg[n] = 0;
    int lane = threadIdx.x & 31;
    const float4* hr = (const float4*)(g_h2 + (size_t)n * RS);
    float4 h0 = __ldg(hr), h1 = __ldg(hr + 1);
    float2 h2 = __ldg((const float2*)(hr + 2));
    float h[10] = {h0.x, h0.y, h0.z, h0.w, h1.x, h1.y, h1.z, h1.w, h2.x, h2.y};
    int b = __ldg(&batch[n]);
    int b0 = __shfl_sync(0xffffffffu, b, 0);
    bool uni = __all_sync(0xffffffffu, b == b0);
    if (uni) {
#pragma unroll
        for (int off = 16; off; off >>= 1)
#pragma unroll
            for (int o = 0; o < 10; o++)
                h[o] += __shfl_xor_sync(0xffffffffu, h[o], off);
        if (lane == 0) {
            float* pp = g_pool + b * RS;
            red_v4(pp,     h[0], h[1], h[2], h[3]);
            red_v4(pp + 4, h[4], h[5], h[6], h[7]);
            red_v4(pp + 8, h[8], h[9], 32.f, 0.f);
        }
    } else {
        float* pp = g_pool + b * RS;
#pragma unroll
        for (int o = 0; o < 10; o++) atomicAdd(&pp[o], h[o]);
        atomicAdd(&pp[10], 1.f);
    }
}

// ---------------------------------------------------------------------------
// Head; restores g_pool = 0 for the next replay.
__global__ void k_head(const float* __restrict__ Wfc, float* __restrict__ out) {
    int b = blockIdx.x * blockDim.x + threadIdx.x;
    if (b >= NB) return;
    float cnt = g_pool[b * RS + 10];
    float inv = 1.f / fmaxf(cnt, 1.f);
    float v = 0.f;
#pragma unroll
    for (int o = 0; o < 10; o++)
        v += g_pool[b * RS + o] * inv * __ldg(&Wfc[o]);
    out[b] = 1.f / (1.f + expf(-v));
#pragma unroll
    for (int o = 0; o < 11; o++) g_pool[b * RS + o] = 0.f;
}

// ---------------------------------------------------------------------------
extern "C" void kernel_launch(void* const* d_in, const int* in_sizes, int n_in,
                              void* d_out, int out_size) {
    const float* x     = (const float*)d_in[0];
    const int*   ei    = (const int*)d_in[1];   // [2, E]
    const int*   batch = (const int*)d_in[2];
    const float* W1    = (const float*)d_in[3]; // [256,10]
    const float* W2    = (const float*)d_in[4]; // [20,10]
    const float* Wfc   = (const float*)d_in[5]; // [10,1]
    float* out = (float*)d_out;

    const int* src = ei;
    const int* dst = ei + NE;

    k_hist<<<(NE / 4 + 255) / 256, 256>>>(dst);                          // 0
    k_scan<<<98, 256>>>();                                               // 1
    k_scatter_gemm<<<SCAT_BLOCKS + GEMM_BLOCKS, 256>>>(src, dst, x, W1); // 2
    k_aggr<0><<<(NN * 32 + 255) / 256, 256>>>(W2);                       // 3 <- profiled
    k_aggr<1><<<(NN * 32 + 255) / 256, 256>>>(W2);                       // 4
    k_final<<<(NN + 255) / 256, 256>>>(batch);                           // 5
    k_head<<<(NB + 255) / 256, 256>>>(Wfc, out);                         // 6
}